// round 7
// baseline (speedup 1.0000x reference)
#include <cuda_runtime.h>
#include <cstdint>

// Problem constants: B=4, S=256, D_MODEL=2048, H=256, HEAD_DIM=8
#define DM     2048
#define MROWS  1024
#define NHEAD  256
#define HD     8
#define SCALE_LOG2E 0.5101594977970228f     // (1/sqrt(8)) * log2(e)

// ---- mma.sync tf32 GEMM tiling: 64x128 CTA tile, 2 CTAs/SM ----
#define BMT 64                  // CTA tile M
#define BNT 128                 // CTA tile N
#define BKT 32                  // CTA tile K
#define NKT (DM / BKT)          // 64 k-tiles
#define STAGES 4
#define A_STRIDE 36             // A smem row stride (floats)
#define B_STRIDE 132            // B smem row stride: frag bank = 8*tr+tg, conflict-free
#define A_TILE_F (BMT * A_STRIDE)       // 2304 floats
#define B_TILE_F (BKT * B_STRIDE)       // 4224 floats
#define SMEM_BYTES (STAGES * (A_TILE_F + B_TILE_F) * 4)   // 104448 B -> 2 CTAs/SM

// ---- device scratch ----
__device__ float g_xr[MROWS * DM];      // tf32-rounded x
__device__ float g_q[MROWS * DM];
__device__ float g_k[MROWS * DM];
__device__ float g_v[MROWS * DM];
__device__ float g_att[MROWS * DM];     // attention output (tf32-rounded)

// ---------------------------------------------------------------------------
// helpers
// ---------------------------------------------------------------------------
__device__ __forceinline__ uint32_t smem_u32(const void* p) {
    uint32_t a;
    asm("{ .reg .u64 t; cvta.to.shared.u64 t, %1; cvt.u32.u64 %0, t; }" : "=r"(a) : "l"(p));
    return a;
}
__device__ __forceinline__ float tf32r(float x) {
    uint32_t u;
    asm("cvt.rna.tf32.f32 %0, %1;" : "=r"(u) : "f"(x));
    return __uint_as_float(u);
}
__device__ __forceinline__ uint32_t tf32b(float x) {
    uint32_t u;
    asm("cvt.rna.tf32.f32 %0, %1;" : "=r"(u) : "f"(x));
    return u;
}
__device__ __forceinline__ float fast_ex2(float x) {
    float r;
    asm("ex2.approx.f32 %0, %1;" : "=f"(r) : "f"(x));
    return r;
}
__device__ __forceinline__ void cp_async16(uint32_t dst, const void* src) {
    asm volatile("cp.async.cg.shared.global [%0], [%1], 16;" :: "r"(dst), "l"(src));
}
#define CP_COMMIT() asm volatile("cp.async.commit_group;" ::: "memory")
#define CP_WAIT(n)  asm volatile("cp.async.wait_group %0;" :: "n"(n) : "memory")

__device__ __forceinline__ void mma_1688(float c[4], const uint32_t a[4], const uint32_t b[2]) {
    asm volatile(
        "mma.sync.aligned.m16n8k8.row.col.f32.tf32.tf32.f32 "
        "{%0,%1,%2,%3}, {%4,%5,%6,%7}, {%8,%9}, {%0,%1,%2,%3};"
        : "+f"(c[0]), "+f"(c[1]), "+f"(c[2]), "+f"(c[3])
        : "r"(a[0]), "r"(a[1]), "r"(a[2]), "r"(a[3]), "r"(b[0]), "r"(b[1]));
}

// ---------------------------------------------------------------------------
// tf32 tensor-core GEMM: C[64,128] tile = A @ W + bias
// A: [M x K] row-major, ALREADY tf32-rounded (g_xr / g_att).
// W: [K x N] row-major (original layout); B smem keeps [k][n]; B fragments =
//    2x LDS.32 + in-register tf32 round. 8 warps: 2(M) x 4(N), warp tile 32x32.
// A fragments use the k-pair permutation: thread tr supplies k-cols (2tr,2tr+1)
// at mma k-positions (tr, tr+4); B matches.
// 4-stage cp.async pipeline, ONE __syncthreads per k-tile:
//   wait(stage kt) -> sync (all warps done with slot kt-1)
//   -> prefetch kt+3 into slot (kt+3)%4 (== (kt-1)%4, now free) -> compute kt.
// ---------------------------------------------------------------------------
__device__ __forceinline__ void gemm_body(const float* __restrict__ A,
                                          const float* __restrict__ W,
                                          const float* __restrict__ bias,
                                          float* __restrict__ C)
{
    extern __shared__ float sm[];
    float* const Asm = sm;                            // [STAGES][A_TILE_F]
    float* const Bsm = sm + STAGES * A_TILE_F;        // [STAGES][B_TILE_F]

    const int tid  = threadIdx.x;
    const int wid  = tid >> 5;
    const int lane = tid & 31;
    const int tg   = lane >> 2;      // 0..7
    const int tr   = lane & 3;       // 0..3
    const int m0   = (wid & 1) * 32;
    const int n0   = (wid >> 1) * 32;
    const int row0 = blockIdx.y * BMT;
    const int col0 = blockIdx.x * BNT;

    const float* gA = A + (size_t)row0 * DM;

    float acc[2][4][4];
#pragma unroll
    for (int mt = 0; mt < 2; mt++)
#pragma unroll
        for (int nt = 0; nt < 4; nt++)
#pragma unroll
            for (int i = 0; i < 4; i++) acc[mt][nt][i] = 0.f;

    // Per stage: A 64 rows x 8 chunks = 512 x 16B; B 32 rows x 32 chunks = 1024.
    // 1536 chunks / 256 threads = 6 per thread (2 A + 4 B).
#define PREFETCH(kt, s)                                                            \
    do {                                                                           \
        float* da = Asm + (s) * A_TILE_F;                                          \
        float* db = Bsm + (s) * B_TILE_F;                                          \
        const float* sa = gA + (kt) * BKT;                                         \
        const float* sw = W + (size_t)((kt) * BKT) * DM + col0;                    \
        _Pragma("unroll")                                                          \
        for (int i = 0; i < 2; i++) {                                              \
            int c4 = tid + i * 256;                                                \
            int ra = c4 >> 3, qa = c4 & 7;                                         \
            cp_async16(smem_u32(da + ra * A_STRIDE + qa * 4),                      \
                       sa + (size_t)ra * DM + qa * 4);                             \
        }                                                                          \
        _Pragma("unroll")                                                          \
        for (int i = 0; i < 4; i++) {                                              \
            int c4 = tid + i * 256;                                                \
            int rb = c4 >> 5, qb = c4 & 31;                                        \
            cp_async16(smem_u32(db + rb * B_STRIDE + qb * 4),                      \
                       sw + (size_t)rb * DM + qb * 4);                             \
        }                                                                          \
    } while (0)

    PREFETCH(0, 0);
    CP_COMMIT();
    PREFETCH(1, 1);
    CP_COMMIT();
    PREFETCH(2, 2);
    CP_COMMIT();

    for (int kt = 0; kt < NKT; kt++) {
        CP_WAIT(STAGES - 2);          // stage kt resident
        __syncthreads();              // + all warps finished slot (kt-1)
        if (kt + 3 < NKT) PREFETCH(kt + 3, (kt + 3) % STAGES);
        CP_COMMIT();                  // always commit to keep group count aligned

        const float* a = Asm + (kt % STAGES) * A_TILE_F;
        const float* b = Bsm + (kt % STAGES) * B_TILE_F;
#pragma unroll
        for (int ks = 0; ks < 4; ks++) {
            const int k0 = ks * 8;
            uint32_t af[2][4], bf[4][2];
#pragma unroll
            for (int mt = 0; mt < 2; mt++) {
                const float* ap = a + (m0 + mt * 16 + tg) * A_STRIDE + k0 + 2 * tr;
                float2 pa = *reinterpret_cast<const float2*>(ap);
                float2 pb = *reinterpret_cast<const float2*>(ap + 8 * A_STRIDE);
                af[mt][0] = __float_as_uint(pa.x);
                af[mt][2] = __float_as_uint(pa.y);
                af[mt][1] = __float_as_uint(pb.x);
                af[mt][3] = __float_as_uint(pb.y);
            }
            const float* b0 = b + (k0 + 2 * tr) * B_STRIDE + n0 + tg;
#pragma unroll
            for (int nt = 0; nt < 4; nt++) {
                bf[nt][0] = tf32b(b0[nt * 8]);
                bf[nt][1] = tf32b(b0[B_STRIDE + nt * 8]);
            }
#pragma unroll
            for (int mt = 0; mt < 2; mt++)
#pragma unroll
                for (int nt = 0; nt < 4; nt++)
                    mma_1688(acc[mt][nt], af[mt], bf[nt]);
        }
    }

#pragma unroll
    for (int mt = 0; mt < 2; mt++) {
        const int r1 = row0 + m0 + mt * 16 + tg;
        const int r2 = r1 + 8;
#pragma unroll
        for (int nt = 0; nt < 4; nt++) {
            const int cb = col0 + n0 + nt * 8 + 2 * tr;
            const float2 bv = *reinterpret_cast<const float2*>(bias + cb);
            float2 o1, o2;
            o1.x = acc[mt][nt][0] + bv.x; o1.y = acc[mt][nt][1] + bv.y;
            o2.x = acc[mt][nt][2] + bv.x; o2.y = acc[mt][nt][3] + bv.y;
            *reinterpret_cast<float2*>(C + (size_t)r1 * DM + cb) = o1;
            *reinterpret_cast<float2*>(C + (size_t)r2 * DM + cb) = o2;
        }
    }
#undef PREFETCH
}

__global__ __launch_bounds__(256, 2)
void qkv_tc(const float* __restrict__ Wq, const float* __restrict__ bq,
            const float* __restrict__ Wk, const float* __restrict__ bk,
            const float* __restrict__ Wv, const float* __restrict__ bv)
{
    const int z = blockIdx.z;
    const float* W    = (z == 0) ? Wq : (z == 1) ? Wk : Wv;
    const float* bias = (z == 0) ? bq : (z == 1) ? bk : bv;
    float* C          = (z == 0) ? g_q : (z == 1) ? g_k : g_v;
    gemm_body(g_xr, W, bias, C);
}

__global__ __launch_bounds__(256, 2)
void out_tc(const float* __restrict__ Wo, const float* __restrict__ bo,
            float* __restrict__ out)
{
    gemm_body(g_att, Wo, bo, out);
}

// x -> tf32-rounded copy (A operand of qkv GEMMs)
__global__ __launch_bounds__(256)
void prep_x(const float* __restrict__ x)
{
    const int i0 = blockIdx.x * 512 + threadIdx.x;
#pragma unroll
    for (int l = 0; l < 2; l++) {
        int i = i0 + l * 256;
        float4 v = reinterpret_cast<const float4*>(x)[i];
        v.x = tf32r(v.x); v.y = tf32r(v.y); v.z = tf32r(v.z); v.w = tf32r(v.w);
        reinterpret_cast<float4*>(g_xr)[i] = v;
    }
}

// ---------------------------------------------------------------------------
// Tensor-core attention. One CTA per (b,s) position m.
// Phase rotation cancels analytically: logits = (q.k)/sqrt(8); attn_i is
// discarded, so phase_shift never reaches the output.
// S = Q@K^T streamed 8 cols at a time (no softmax max: logits O(+-5));
// P fed from registers into the PV mma via the k-pair permutation.
// Output tf32-rounded (A operand of the out-projection).
// ---------------------------------------------------------------------------
__global__ __launch_bounds__(256)
void attn_tc()
{
    __shared__ float QT[8][264];   // [d][head]
    __shared__ float KT[8][264];
    __shared__ float VT[8][264];

    const int m    = blockIdx.x;
    const int t    = threadIdx.x;
    const int w    = t >> 5;
    const int lane = t & 31;
    const int tg   = lane >> 2;
    const int tr   = lane & 3;
    const int m0w  = w * 32;

    {
        const float4* q4 = reinterpret_cast<const float4*>(g_q + (size_t)m * DM) + 2 * t;
        const float4* k4 = reinterpret_cast<const float4*>(g_k + (size_t)m * DM) + 2 * t;
        const float4* v4 = reinterpret_cast<const float4*>(g_v + (size_t)m * DM) + 2 * t;
        float4 a0 = q4[0], a1 = q4[1];
        QT[0][t] = tf32r(a0.x); QT[1][t] = tf32r(a0.y);
        QT[2][t] = tf32r(a0.z); QT[3][t] = tf32r(a0.w);
        QT[4][t] = tf32r(a1.x); QT[5][t] = tf32r(a1.y);
        QT[6][t] = tf32r(a1.z); QT[7][t] = tf32r(a1.w);
        a0 = k4[0]; a1 = k4[1];
        KT[0][t] = tf32r(a0.x); KT[1][t] = tf32r(a0.y);
        KT[2][t] = tf32r(a0.z); KT[3][t] = tf32r(a0.w);
        KT[4][t] = tf32r(a1.x); KT[5][t] = tf32r(a1.y);
        KT[6][t] = tf32r(a1.z); KT[7][t] = tf32r(a1.w);
        a0 = v4[0]; a1 = v4[1];
        VT[0][t] = tf32r(a0.x); VT[1][t] = tf32r(a0.y);
        VT[2][t] = tf32r(a0.z); VT[3][t] = tf32r(a0.w);
        VT[4][t] = tf32r(a1.x); VT[5][t] = tf32r(a1.y);
        VT[6][t] = tf32r(a1.z); VT[7][t] = tf32r(a1.w);
    }
    __syncthreads();

    uint32_t aq0[4], aq1[4];
    aq0[0] = __float_as_uint(QT[tr    ][m0w + tg     ]);
    aq0[1] = __float_as_uint(QT[tr    ][m0w + tg +  8]);
    aq0[2] = __float_as_uint(QT[tr + 4][m0w + tg     ]);
    aq0[3] = __float_as_uint(QT[tr + 4][m0w + tg +  8]);
    aq1[0] = __float_as_uint(QT[tr    ][m0w + tg + 16]);
    aq1[1] = __float_as_uint(QT[tr    ][m0w + tg + 24]);
    aq1[2] = __float_as_uint(QT[tr + 4][m0w + tg + 16]);
    aq1[3] = __float_as_uint(QT[tr + 4][m0w + tg + 24]);

    float l[4] = {0.f, 0.f, 0.f, 0.f};
    float out0[4] = {0.f, 0.f, 0.f, 0.f};
    float out1[4] = {0.f, 0.f, 0.f, 0.f};

    for (int nt = 0; nt < 32; nt++) {
        const int g0 = nt * 8;
        uint32_t bs[2];
        bs[0] = __float_as_uint(KT[tr    ][g0 + tg]);
        bs[1] = __float_as_uint(KT[tr + 4][g0 + tg]);

        float c0[4] = {0.f, 0.f, 0.f, 0.f};
        float c1[4] = {0.f, 0.f, 0.f, 0.f};
        mma_1688(c0, aq0, bs);
        mma_1688(c1, aq1, bs);

        float p00 = fast_ex2(c0[0] * SCALE_LOG2E);
        float p01 = fast_ex2(c0[1] * SCALE_LOG2E);
        float p02 = fast_ex2(c0[2] * SCALE_LOG2E);
        float p03 = fast_ex2(c0[3] * SCALE_LOG2E);
        float p10 = fast_ex2(c1[0] * SCALE_LOG2E);
        float p11 = fast_ex2(c1[1] * SCALE_LOG2E);
        float p12 = fast_ex2(c1[2] * SCALE_LOG2E);
        float p13 = fast_ex2(c1[3] * SCALE_LOG2E);
        l[0] += p00 + p01;
        l[1] += p02 + p03;
        l[2] += p10 + p11;
        l[3] += p12 + p13;

        float2 vv = *reinterpret_cast<const float2*>(&VT[tg][g0 + 2 * tr]);
        uint32_t bv[2];
        bv[0] = __float_as_uint(vv.x);
        bv[1] = __float_as_uint(vv.y);

        uint32_t ap0[4], ap1[4];
        ap0[0] = tf32b(p00); ap0[1] = tf32b(p02); ap0[2] = tf32b(p01); ap0[3] = tf32b(p03);
        ap1[0] = tf32b(p10); ap1[1] = tf32b(p12); ap1[2] = tf32b(p11); ap1[3] = tf32b(p13);
        mma_1688(out0, ap0, bv);
        mma_1688(out1, ap1, bv);
    }

#pragma unroll
    for (int i = 0; i < 4; i++) {
        l[i] += __shfl_xor_sync(0xFFFFFFFFu, l[i], 1);
        l[i] += __shfl_xor_sync(0xFFFFFFFFu, l[i], 2);
    }
    const float i0 = 1.f / l[0], i1 = 1.f / l[1], i2 = 1.f / l[2], i3 = 1.f / l[3];

    float* base = g_att + (size_t)m * DM + 2 * tr;
    float2 o;
    o.x = tf32r(out0[0] * i0); o.y = tf32r(out0[1] * i0);
    *reinterpret_cast<float2*>(base + (m0w + tg     ) * HD) = o;
    o.x = tf32r(out0[2] * i1); o.y = tf32r(out0[3] * i1);
    *reinterpret_cast<float2*>(base + (m0w + tg +  8) * HD) = o;
    o.x = tf32r(out1[0] * i2); o.y = tf32r(out1[1] * i2);
    *reinterpret_cast<float2*>(base + (m0w + tg + 16) * HD) = o;
    o.x = tf32r(out1[2] * i3); o.y = tf32r(out1[3] * i3);
    *reinterpret_cast<float2*>(base + (m0w + tg + 24) * HD) = o;
}

// ---------------------------------------------------------------------------
// Launch
// ---------------------------------------------------------------------------
extern "C" void kernel_launch(void* const* d_in, const int* in_sizes, int n_in,
                              void* d_out, int out_size)
{
    const float* x  = (const float*)d_in[0];
    // d_in[1] = phase_shift: cancels analytically, unused.
    const float* Wq = (const float*)d_in[2];
    const float* bq = (const float*)d_in[3];
    const float* Wk = (const float*)d_in[4];
    const float* bk = (const float*)d_in[5];
    const float* Wv = (const float*)d_in[6];
    const float* bv = (const float*)d_in[7];
    const float* Wo = (const float*)d_in[8];
    const float* bo = (const float*)d_in[9];
    float* out = (float*)d_out;

    cudaFuncSetAttribute(qkv_tc, cudaFuncAttributeMaxDynamicSharedMemorySize, SMEM_BYTES);
    cudaFuncSetAttribute(out_tc, cudaFuncAttributeMaxDynamicSharedMemorySize, SMEM_BYTES);

    prep_x<<<MROWS * DM / 512, 256>>>(x);

    dim3 qkv_grid(DM / BNT, MROWS / BMT, 3);     // (16, 16, 3) = 768 CTAs
    qkv_tc<<<qkv_grid, 256, SMEM_BYTES>>>(Wq, bq, Wk, bk, Wv, bv);

    attn_tc<<<MROWS, 256>>>();

    dim3 out_grid(DM / BNT, MROWS / BMT);        // (16, 16) = 256 CTAs
    out_tc<<<out_grid, 256, SMEM_BYTES>>>(Wo, bo, out);
}

// round 8
// speedup vs baseline: 1.3208x; 1.3208x over previous
#include <cuda_runtime.h>
#include <cstdint>

// Problem constants: B=4, S=256, D_MODEL=2048, H=256, HEAD_DIM=8
#define DM     2048
#define MROWS  1024
#define NHEAD  256
#define HD     8
#define SCALE_LOG2E 0.5101594977970228f     // (1/sqrt(8)) * log2(e)

// ---- mma.sync tf32 GEMM tiling: 128x128 CTA tile, target 2 CTAs/SM ----
#define BMT 128                 // CTA tile M
#define BNT 128                 // CTA tile N
#define BKT 32                  // CTA tile K
#define STAGES 3
#define A_STRIDE 40             // bank(frag) = 8*tg+2*tr: conflict-free LDS.64
#define B_STRIDE 132            // bank(frag) = 8*tr+tg: conflict-free LDS.32
#define A_TILE_F (BMT * A_STRIDE)       // 5120 floats
#define B_TILE_F (BKT * B_STRIDE)       // 4224 floats
#define SMEM_BYTES (STAGES * (A_TILE_F + B_TILE_F) * 4)   // 112128 B; x2 = 224 KB/SM

// ---- device scratch ----
__device__ float g_xr[MROWS * DM];      // tf32-rounded x
__device__ float g_q[MROWS * DM];       // q ; later reused as out split-K partial 0
__device__ float g_k[MROWS * DM];       // k ; later reused as out split-K partial 1
__device__ float g_v[MROWS * DM];
__device__ float g_att[MROWS * DM];     // attention output (tf32-rounded)

// ---------------------------------------------------------------------------
// helpers
// ---------------------------------------------------------------------------
__device__ __forceinline__ uint32_t smem_u32(const void* p) {
    uint32_t a;
    asm("{ .reg .u64 t; cvta.to.shared.u64 t, %1; cvt.u32.u64 %0, t; }" : "=r"(a) : "l"(p));
    return a;
}
__device__ __forceinline__ float tf32r(float x) {
    uint32_t u;
    asm("cvt.rna.tf32.f32 %0, %1;" : "=r"(u) : "f"(x));
    return __uint_as_float(u);
}
__device__ __forceinline__ uint32_t tf32b(float x) {
    uint32_t u;
    asm("cvt.rna.tf32.f32 %0, %1;" : "=r"(u) : "f"(x));
    return u;
}
__device__ __forceinline__ float fast_ex2(float x) {
    float r;
    asm("ex2.approx.f32 %0, %1;" : "=f"(r) : "f"(x));
    return r;
}
__device__ __forceinline__ void cp_async16(uint32_t dst, const void* src) {
    asm volatile("cp.async.cg.shared.global [%0], [%1], 16;" :: "r"(dst), "l"(src));
}
#define CP_COMMIT() asm volatile("cp.async.commit_group;" ::: "memory")
#define CP_WAIT(n)  asm volatile("cp.async.wait_group %0;" :: "n"(n) : "memory")

__device__ __forceinline__ void mma_1688(float c[4], const uint32_t a[4], const uint32_t b[2]) {
    asm volatile(
        "mma.sync.aligned.m16n8k8.row.col.f32.tf32.tf32.f32 "
        "{%0,%1,%2,%3}, {%4,%5,%6,%7}, {%8,%9}, {%0,%1,%2,%3};"
        : "+f"(c[0]), "+f"(c[1]), "+f"(c[2]), "+f"(c[3])
        : "r"(a[0]), "r"(a[1]), "r"(a[2]), "r"(a[3]), "r"(b[0]), "r"(b[1]));
}

// ---------------------------------------------------------------------------
// tf32 tensor-core GEMM: C[128,128] tile = A[:, koff:koff+nkt*32] @ W + bias
// A: [M x K] row-major, ALREADY tf32-rounded (g_xr / g_att).
// W: [K x N] row-major (original layout); B smem keeps [k][n]; B fragments =
//    2x LDS.32 + in-register tf32 round. 8 warps: 2(M) x 4(N), warp tile 64x32.
// A fragments use the k-pair permutation: thread tr supplies k-cols (2tr,2tr+1)
// at mma k-positions (tr, tr+4); B matches.
// 3-stage cp.async pipeline, ONE __syncthreads per k-tile.
// ---------------------------------------------------------------------------
__device__ __forceinline__ void gemm_body(const float* __restrict__ A,
                                          const float* __restrict__ W,
                                          const float* __restrict__ bias,
                                          float* __restrict__ C,
                                          int koff, int nkt)
{
    extern __shared__ float sm[];
    float* const Asm = sm;                            // [STAGES][A_TILE_F]
    float* const Bsm = sm + STAGES * A_TILE_F;        // [STAGES][B_TILE_F]

    const int tid  = threadIdx.x;
    const int wid  = tid >> 5;
    const int lane = tid & 31;
    const int tg   = lane >> 2;      // 0..7
    const int tr   = lane & 3;       // 0..3
    const int m0   = (wid & 1) * 64;
    const int n0   = (wid >> 1) * 32;
    const int row0 = blockIdx.y * BMT;
    const int col0 = blockIdx.x * BNT;

    const float* gA = A + (size_t)row0 * DM + koff;
    const float* gW = W + (size_t)koff * DM + col0;

    float acc[4][4][4];
#pragma unroll
    for (int mt = 0; mt < 4; mt++)
#pragma unroll
        for (int nt = 0; nt < 4; nt++)
#pragma unroll
            for (int i = 0; i < 4; i++) acc[mt][nt][i] = 0.f;

    // Per stage: A 128 rows x 8 chunks = 1024 x 16B; B 32 rows x 32 chunks = 1024.
    // 2048 chunks / 256 threads = 8 per thread (4 A + 4 B).
#define PREFETCH(kt, s)                                                            \
    do {                                                                           \
        float* da = Asm + (s) * A_TILE_F;                                          \
        float* db = Bsm + (s) * B_TILE_F;                                          \
        const float* sa = gA + (kt) * BKT;                                         \
        const float* sw = gW + (size_t)((kt) * BKT) * DM;                          \
        _Pragma("unroll")                                                          \
        for (int i = 0; i < 4; i++) {                                              \
            int c4 = tid + i * 256;                                                \
            int ra = c4 >> 3, qa = c4 & 7;                                         \
            cp_async16(smem_u32(da + ra * A_STRIDE + qa * 4),                      \
                       sa + (size_t)ra * DM + qa * 4);                             \
            int rb = c4 >> 5, qb = c4 & 31;                                        \
            cp_async16(smem_u32(db + rb * B_STRIDE + qb * 4),                      \
                       sw + (size_t)rb * DM + qb * 4);                             \
        }                                                                          \
    } while (0)

    PREFETCH(0, 0);
    CP_COMMIT();
    PREFETCH(1, 1);
    CP_COMMIT();

    for (int kt = 0; kt < nkt; kt++) {
        CP_WAIT(STAGES - 2);          // stage kt resident
        __syncthreads();              // + all warps finished slot (kt-1)
        if (kt + 2 < nkt) PREFETCH(kt + 2, (kt + 2) % STAGES);
        CP_COMMIT();                  // always commit: keeps group count aligned

        const float* a = Asm + (kt % STAGES) * A_TILE_F;
        const float* b = Bsm + (kt % STAGES) * B_TILE_F;
#pragma unroll
        for (int ks = 0; ks < 4; ks++) {
            const int k0 = ks * 8;
            uint32_t af[4][4], bf[4][2];
#pragma unroll
            for (int mt = 0; mt < 4; mt++) {
                const float* ap = a + (m0 + mt * 16 + tg) * A_STRIDE + k0 + 2 * tr;
                float2 pa = *reinterpret_cast<const float2*>(ap);
                float2 pb = *reinterpret_cast<const float2*>(ap + 8 * A_STRIDE);
                af[mt][0] = __float_as_uint(pa.x);
                af[mt][2] = __float_as_uint(pa.y);
                af[mt][1] = __float_as_uint(pb.x);
                af[mt][3] = __float_as_uint(pb.y);
            }
            const float* b0 = b + (k0 + 2 * tr) * B_STRIDE + n0 + tg;
#pragma unroll
            for (int nt = 0; nt < 4; nt++) {
                bf[nt][0] = tf32b(b0[nt * 8]);
                bf[nt][1] = tf32b(b0[B_STRIDE + nt * 8]);
            }
#pragma unroll
            for (int mt = 0; mt < 4; mt++)
#pragma unroll
                for (int nt = 0; nt < 4; nt++)
                    mma_1688(acc[mt][nt], af[mt], bf[nt]);
        }
    }

#pragma unroll
    for (int mt = 0; mt < 4; mt++) {
        const int r1 = row0 + m0 + mt * 16 + tg;
        const int r2 = r1 + 8;
#pragma unroll
        for (int nt = 0; nt < 4; nt++) {
            const int cb = col0 + n0 + nt * 8 + 2 * tr;
            float2 bv = {0.f, 0.f};
            if (bias) bv = *reinterpret_cast<const float2*>(bias + cb);
            float2 o1, o2;
            o1.x = acc[mt][nt][0] + bv.x; o1.y = acc[mt][nt][1] + bv.y;
            o2.x = acc[mt][nt][2] + bv.x; o2.y = acc[mt][nt][3] + bv.y;
            *reinterpret_cast<float2*>(C + (size_t)r1 * DM + cb) = o1;
            *reinterpret_cast<float2*>(C + (size_t)r2 * DM + cb) = o2;
        }
    }
#undef PREFETCH
}

__global__ __launch_bounds__(256, 2)
void qkv_tc(const float* __restrict__ Wq, const float* __restrict__ bq,
            const float* __restrict__ Wk, const float* __restrict__ bk,
            const float* __restrict__ Wv, const float* __restrict__ bv)
{
    const int z = blockIdx.z;
    const float* W    = (z == 0) ? Wq : (z == 1) ? Wk : Wv;
    const float* bias = (z == 0) ? bq : (z == 1) ? bk : bv;
    float* C          = (z == 0) ? g_q : (z == 1) ? g_k : g_v;
    gemm_body(g_xr, W, bias, C, 0, DM / BKT);
}

// out projection split-K=2: z=0 -> K[0,1024) into g_q ; z=1 -> K[1024,2048) into g_k
// (g_q/g_k are dead after attn_tc). Deterministic reduce adds them + bias.
__global__ __launch_bounds__(256, 2)
void out_tc_split(const float* __restrict__ Wo)
{
    const int z = blockIdx.z;
    float* C = (z == 0) ? g_q : g_k;
    gemm_body(g_att, Wo, nullptr, C, z * (DM / 2), DM / (2 * BKT));
}

__global__ __launch_bounds__(256)
void reduce_out(const float* __restrict__ bo, float* __restrict__ out)
{
    const int i = blockIdx.x * blockDim.x + threadIdx.x;      // float4 index
    const float4 a = reinterpret_cast<const float4*>(g_q)[i];
    const float4 b = reinterpret_cast<const float4*>(g_k)[i];
    const float4 bv = reinterpret_cast<const float4*>(bo)[i & (DM / 4 - 1)];
    float4 o;
    o.x = a.x + b.x + bv.x; o.y = a.y + b.y + bv.y;
    o.z = a.z + b.z + bv.z; o.w = a.w + b.w + bv.w;
    reinterpret_cast<float4*>(out)[i] = o;
}

// x -> tf32-rounded copy (A operand of qkv GEMMs)
__global__ __launch_bounds__(256)
void prep_x(const float* __restrict__ x)
{
    const int i0 = blockIdx.x * 512 + threadIdx.x;
#pragma unroll
    for (int l = 0; l < 2; l++) {
        int i = i0 + l * 256;
        float4 v = reinterpret_cast<const float4*>(x)[i];
        v.x = tf32r(v.x); v.y = tf32r(v.y); v.z = tf32r(v.z); v.w = tf32r(v.w);
        reinterpret_cast<float4*>(g_xr)[i] = v;
    }
}

// ---------------------------------------------------------------------------
// Tensor-core attention. One CTA per (b,s) position m.
// Phase rotation cancels analytically: logits = (q.k)/sqrt(8); attn_i is
// discarded, so phase_shift never reaches the output.
// S = Q@K^T streamed 8 cols at a time (no softmax max: logits O(+-5));
// P fed from registers into the PV mma via the k-pair permutation.
// Output tf32-rounded (A operand of the out-projection).
// ---------------------------------------------------------------------------
__global__ __launch_bounds__(256)
void attn_tc()
{
    __shared__ float QT[8][264];   // [d][head]
    __shared__ float KT[8][264];
    __shared__ float VT[8][264];

    const int m    = blockIdx.x;
    const int t    = threadIdx.x;
    const int w    = t >> 5;
    const int lane = t & 31;
    const int tg   = lane >> 2;
    const int tr   = lane & 3;
    const int m0w  = w * 32;

    {
        const float4* q4 = reinterpret_cast<const float4*>(g_q + (size_t)m * DM) + 2 * t;
        const float4* k4 = reinterpret_cast<const float4*>(g_k + (size_t)m * DM) + 2 * t;
        const float4* v4 = reinterpret_cast<const float4*>(g_v + (size_t)m * DM) + 2 * t;
        float4 a0 = q4[0], a1 = q4[1];
        QT[0][t] = tf32r(a0.x); QT[1][t] = tf32r(a0.y);
        QT[2][t] = tf32r(a0.z); QT[3][t] = tf32r(a0.w);
        QT[4][t] = tf32r(a1.x); QT[5][t] = tf32r(a1.y);
        QT[6][t] = tf32r(a1.z); QT[7][t] = tf32r(a1.w);
        a0 = k4[0]; a1 = k4[1];
        KT[0][t] = tf32r(a0.x); KT[1][t] = tf32r(a0.y);
        KT[2][t] = tf32r(a0.z); KT[3][t] = tf32r(a0.w);
        KT[4][t] = tf32r(a1.x); KT[5][t] = tf32r(a1.y);
        KT[6][t] = tf32r(a1.z); KT[7][t] = tf32r(a1.w);
        a0 = v4[0]; a1 = v4[1];
        VT[0][t] = tf32r(a0.x); VT[1][t] = tf32r(a0.y);
        VT[2][t] = tf32r(a0.z); VT[3][t] = tf32r(a0.w);
        VT[4][t] = tf32r(a1.x); VT[5][t] = tf32r(a1.y);
        VT[6][t] = tf32r(a1.z); VT[7][t] = tf32r(a1.w);
    }
    __syncthreads();

    uint32_t aq0[4], aq1[4];
    aq0[0] = __float_as_uint(QT[tr    ][m0w + tg     ]);
    aq0[1] = __float_as_uint(QT[tr    ][m0w + tg +  8]);
    aq0[2] = __float_as_uint(QT[tr + 4][m0w + tg     ]);
    aq0[3] = __float_as_uint(QT[tr + 4][m0w + tg +  8]);
    aq1[0] = __float_as_uint(QT[tr    ][m0w + tg + 16]);
    aq1[1] = __float_as_uint(QT[tr    ][m0w + tg + 24]);
    aq1[2] = __float_as_uint(QT[tr + 4][m0w + tg + 16]);
    aq1[3] = __float_as_uint(QT[tr + 4][m0w + tg + 24]);

    float l[4] = {0.f, 0.f, 0.f, 0.f};
    float out0[4] = {0.f, 0.f, 0.f, 0.f};
    float out1[4] = {0.f, 0.f, 0.f, 0.f};

    for (int nt = 0; nt < 32; nt++) {
        const int g0 = nt * 8;
        uint32_t bs[2];
        bs[0] = __float_as_uint(KT[tr    ][g0 + tg]);
        bs[1] = __float_as_uint(KT[tr + 4][g0 + tg]);

        float c0[4] = {0.f, 0.f, 0.f, 0.f};
        float c1[4] = {0.f, 0.f, 0.f, 0.f};
        mma_1688(c0, aq0, bs);
        mma_1688(c1, aq1, bs);

        float p00 = fast_ex2(c0[0] * SCALE_LOG2E);
        float p01 = fast_ex2(c0[1] * SCALE_LOG2E);
        float p02 = fast_ex2(c0[2] * SCALE_LOG2E);
        float p03 = fast_ex2(c0[3] * SCALE_LOG2E);
        float p10 = fast_ex2(c1[0] * SCALE_LOG2E);
        float p11 = fast_ex2(c1[1] * SCALE_LOG2E);
        float p12 = fast_ex2(c1[2] * SCALE_LOG2E);
        float p13 = fast_ex2(c1[3] * SCALE_LOG2E);
        l[0] += p00 + p01;
        l[1] += p02 + p03;
        l[2] += p10 + p11;
        l[3] += p12 + p13;

        float2 vv = *reinterpret_cast<const float2*>(&VT[tg][g0 + 2 * tr]);
        uint32_t bv[2];
        bv[0] = __float_as_uint(vv.x);
        bv[1] = __float_as_uint(vv.y);

        uint32_t ap0[4], ap1[4];
        ap0[0] = tf32b(p00); ap0[1] = tf32b(p02); ap0[2] = tf32b(p01); ap0[3] = tf32b(p03);
        ap1[0] = tf32b(p10); ap1[1] = tf32b(p12); ap1[2] = tf32b(p11); ap1[3] = tf32b(p13);
        mma_1688(out0, ap0, bv);
        mma_1688(out1, ap1, bv);
    }

#pragma unroll
    for (int i = 0; i < 4; i++) {
        l[i] += __shfl_xor_sync(0xFFFFFFFFu, l[i], 1);
        l[i] += __shfl_xor_sync(0xFFFFFFFFu, l[i], 2);
    }
    const float i0 = 1.f / l[0], i1 = 1.f / l[1], i2 = 1.f / l[2], i3 = 1.f / l[3];

    float* base = g_att + (size_t)m * DM + 2 * tr;
    float2 o;
    o.x = tf32r(out0[0] * i0); o.y = tf32r(out0[1] * i0);
    *reinterpret_cast<float2*>(base + (m0w + tg     ) * HD) = o;
    o.x = tf32r(out0[2] * i1); o.y = tf32r(out0[3] * i1);
    *reinterpret_cast<float2*>(base + (m0w + tg +  8) * HD) = o;
    o.x = tf32r(out1[0] * i2); o.y = tf32r(out1[1] * i2);
    *reinterpret_cast<float2*>(base + (m0w + tg + 16) * HD) = o;
    o.x = tf32r(out1[2] * i3); o.y = tf32r(out1[3] * i3);
    *reinterpret_cast<float2*>(base + (m0w + tg + 24) * HD) = o;
}

// ---------------------------------------------------------------------------
// Launch
// ---------------------------------------------------------------------------
extern "C" void kernel_launch(void* const* d_in, const int* in_sizes, int n_in,
                              void* d_out, int out_size)
{
    const float* x  = (const float*)d_in[0];
    // d_in[1] = phase_shift: cancels analytically, unused.
    const float* Wq = (const float*)d_in[2];
    const float* bq = (const float*)d_in[3];
    const float* Wk = (const float*)d_in[4];
    const float* bk = (const float*)d_in[5];
    const float* Wv = (const float*)d_in[6];
    const float* bv = (const float*)d_in[7];
    const float* Wo = (const float*)d_in[8];
    const float* bo = (const float*)d_in[9];
    float* out = (float*)d_out;

    cudaFuncSetAttribute(qkv_tc, cudaFuncAttributeMaxDynamicSharedMemorySize, SMEM_BYTES);
    cudaFuncSetAttribute(out_tc_split, cudaFuncAttributeMaxDynamicSharedMemorySize, SMEM_BYTES);

    prep_x<<<MROWS * DM / 2048, 256>>>(x);           // 1024 blocks, exact cover

    dim3 qkv_grid(DM / BNT, MROWS / BMT, 3);         // (16, 8, 3) = 384 CTAs
    qkv_tc<<<qkv_grid, 256, SMEM_BYTES>>>(Wq, bq, Wk, bk, Wv, bv);

    attn_tc<<<MROWS, 256>>>();

    dim3 out_grid(DM / BNT, MROWS / BMT, 2);         // (16, 8, 2) = 256 CTAs
    out_tc_split<<<out_grid, 256, SMEM_BYTES>>>(Wo);

    reduce_out<<<(MROWS * DM / 4) / 256, 256>>>(bo, out);
}

// round 9
// speedup vs baseline: 1.9180x; 1.4522x over previous
#include <cuda_runtime.h>
#include <cuda_fp16.h>
#include <cstdint>

// Problem constants: B=4, S=256, D_MODEL=2048, H=256, HEAD_DIM=8
#define DM     2048
#define MROWS  1024
#define NHEAD  256
#define HD     8
#define SCALE_LOG2E 0.5101594977970228f     // (1/sqrt(8)) * log2(e)

// ---- fp16 mma.sync GEMM tiling: 128x128 CTA tile, 2 CTAs/SM ----
#define BMT 128
#define BNT 128
#define BKT 32                  // k-halves per tile (2 x k16 mma steps)
#define STAGES 4
#define HSTRIDE 48              // smem row stride in halves (96B): frag bank = 24tg+2tr, conflict-free
#define TILE_H (128 * HSTRIDE)  // 6144 halves = 12288 B per operand per stage
#define SMEM_BYTES (STAGES * 2 * TILE_H * 2)   // 98304 B; x2 CTAs = 192 KB/SM

// ---- device scratch ----
__device__ __half g_xh[MROWS * DM];        // fp16 x  [m][k]
__device__ __half g_wh[4][DM * DM];        // fp16 W^T [n][k]: Wq,Wk,Wv,Wo
__device__ __half g_ath[MROWS * DM];       // fp16 attention output [m][k]
__device__ float  g_q[MROWS * DM];         // q ; later reused as out split-K partial 0
__device__ float  g_k[MROWS * DM];         // k ; later reused as out split-K partial 1
__device__ float  g_v[MROWS * DM];

// ---------------------------------------------------------------------------
// helpers
// ---------------------------------------------------------------------------
__device__ __forceinline__ uint32_t smem_u32(const void* p) {
    uint32_t a;
    asm("{ .reg .u64 t; cvta.to.shared.u64 t, %1; cvt.u32.u64 %0, t; }" : "=r"(a) : "l"(p));
    return a;
}
__device__ __forceinline__ float tf32r(float x) {
    uint32_t u;
    asm("cvt.rna.tf32.f32 %0, %1;" : "=r"(u) : "f"(x));
    return __uint_as_float(u);
}
__device__ __forceinline__ uint32_t tf32b(float x) {
    uint32_t u;
    asm("cvt.rna.tf32.f32 %0, %1;" : "=r"(u) : "f"(x));
    return u;
}
__device__ __forceinline__ float fast_ex2(float x) {
    float r;
    asm("ex2.approx.f32 %0, %1;" : "=f"(r) : "f"(x));
    return r;
}
__device__ __forceinline__ void cp_async16(uint32_t dst, const void* src) {
    asm volatile("cp.async.cg.shared.global [%0], [%1], 16;" :: "r"(dst), "l"(src));
}
#define CP_COMMIT() asm volatile("cp.async.commit_group;" ::: "memory")
#define CP_WAIT(n)  asm volatile("cp.async.wait_group %0;" :: "n"(n) : "memory")

// tf32 m16n8k8 (attention only)
__device__ __forceinline__ void mma_1688(float c[4], const uint32_t a[4], const uint32_t b[2]) {
    asm volatile(
        "mma.sync.aligned.m16n8k8.row.col.f32.tf32.tf32.f32 "
        "{%0,%1,%2,%3}, {%4,%5,%6,%7}, {%8,%9}, {%0,%1,%2,%3};"
        : "+f"(c[0]), "+f"(c[1]), "+f"(c[2]), "+f"(c[3])
        : "r"(a[0]), "r"(a[1]), "r"(a[2]), "r"(a[3]), "r"(b[0]), "r"(b[1]));
}
// fp16 m16n8k16, f32 accumulate (GEMMs)
__device__ __forceinline__ void mma_16816(float c[4],
                                          uint32_t a0, uint32_t a1, uint32_t a2, uint32_t a3,
                                          uint32_t b0, uint32_t b1) {
    asm volatile(
        "mma.sync.aligned.m16n8k16.row.col.f32.f16.f16.f32 "
        "{%0,%1,%2,%3}, {%4,%5,%6,%7}, {%8,%9}, {%0,%1,%2,%3};"
        : "+f"(c[0]), "+f"(c[1]), "+f"(c[2]), "+f"(c[3])
        : "r"(a0), "r"(a1), "r"(a2), "r"(a3), "r"(b0), "r"(b1));
}

// ---------------------------------------------------------------------------
// fp16 tensor-core GEMM: C[128,128] f32 tile = A @ Bw^T + bias
// A: fp16 [M][K] row-major. Bw: fp16 [N][K] row-major (pre-transposed W).
// 8 warps: 2(M) x 4(N), warp tile 64x32.
// k-permutation: mma k-positions {2tr,2tr+1} <- data cols {4tr,4tr+1};
//                positions {2tr+8,2tr+9} <- cols {4tr+2,4tr+3}.
// So ONE LDS.64 per row yields (a0,a2) / (a1,a3) / (b0,b1).
// cp.async fill uses a bijective chunk remap: 16B-store banks conflict-free.
// 4-stage pipeline, ONE __syncthreads per k-tile.
// ---------------------------------------------------------------------------
__device__ __forceinline__ void gemm_body(const __half* __restrict__ A,
                                          const __half* __restrict__ Bw,
                                          const float* __restrict__ bias,
                                          float* __restrict__ C,
                                          int koff, int nkt)
{
    extern __shared__ __half smh[];
    __half* const Asm = smh;                          // [STAGES][TILE_H]
    __half* const Bsm = smh + STAGES * TILE_H;

    const int tid  = threadIdx.x;
    const int wid  = tid >> 5;
    const int lane = tid & 31;
    const int tg   = lane >> 2;      // 0..7
    const int tr   = lane & 3;       // 0..3
    const int m0   = (wid & 1) * 64;
    const int n0   = (wid >> 1) * 32;
    const int row0 = blockIdx.y * BMT;
    const int col0 = blockIdx.x * BNT;

    const __half* gA = A  + (size_t)row0 * DM + koff;
    const __half* gB = Bw + (size_t)col0 * DM + koff;

    float acc[4][4][4];
#pragma unroll
    for (int mt = 0; mt < 4; mt++)
#pragma unroll
        for (int nt = 0; nt < 4; nt++)
#pragma unroll
            for (int i = 0; i < 4; i++) acc[mt][nt][i] = 0.f;

    // Per stage per operand: 128 rows x 64B = 512 x 16B chunks; 1024 total.
    // Bijective remap c -> (row, qb): row = ((c>>1)&3) | (((c>>3)&31)<<2),
    // qb = (c&1) | (((c>>8)&1)<<1). Makes each 8-lane store phase hit 8
    // distinct 16B bank groups (addr mod 128 all distinct).
#define PREFETCH(kt, s)                                                            \
    do {                                                                           \
        __half* da = Asm + (s) * TILE_H;                                           \
        __half* db = Bsm + (s) * TILE_H;                                           \
        const __half* sa = gA + (kt) * BKT;                                        \
        const __half* sb = gB + (kt) * BKT;                                        \
        _Pragma("unroll")                                                          \
        for (int i = 0; i < 2; i++) {                                              \
            int c = tid + i * 256;                                                 \
            int r = ((c >> 1) & 3) | (((c >> 3) & 31) << 2);                       \
            int q = (c & 1) | (((c >> 8) & 1) << 1);                               \
            cp_async16(smem_u32(da + r * HSTRIDE + q * 8),                         \
                       sa + (size_t)r * DM + q * 8);                               \
        }                                                                          \
        _Pragma("unroll")                                                          \
        for (int i = 0; i < 2; i++) {                                              \
            int c = tid + i * 256;                                                 \
            int r = ((c >> 1) & 3) | (((c >> 3) & 31) << 2);                       \
            int q = (c & 1) | (((c >> 8) & 1) << 1);                               \
            cp_async16(smem_u32(db + r * HSTRIDE + q * 8),                         \
                       sb + (size_t)r * DM + q * 8);                               \
        }                                                                          \
    } while (0)

    PREFETCH(0, 0);
    CP_COMMIT();
    PREFETCH(1, 1);
    CP_COMMIT();
    PREFETCH(2, 2);
    CP_COMMIT();

    for (int kt = 0; kt < nkt; kt++) {
        CP_WAIT(STAGES - 2);          // stage kt resident
        __syncthreads();              // + all warps done with slot (kt-1)
        if (kt + 3 < nkt) PREFETCH(kt + 3, (kt + 3) % STAGES);
        CP_COMMIT();                  // always commit: keeps group count aligned

        const __half* a = Asm + (kt % STAGES) * TILE_H;
        const __half* b = Bsm + (kt % STAGES) * TILE_H;
#pragma unroll
        for (int ks = 0; ks < 2; ks++) {              // 2 x k16 per k-tile
            const int k0 = ks * 16;
            uint2 au[4][2];
            uint2 bu[4];
#pragma unroll
            for (int mt = 0; mt < 4; mt++) {
                const __half* ap = a + (m0 + mt * 16 + tg) * HSTRIDE + k0 + 4 * tr;
                au[mt][0] = *reinterpret_cast<const uint2*>(ap);               // row tg
                au[mt][1] = *reinterpret_cast<const uint2*>(ap + 8 * HSTRIDE); // row tg+8
            }
#pragma unroll
            for (int nt = 0; nt < 4; nt++) {
                const __half* bp = b + (n0 + nt * 8 + tg) * HSTRIDE + k0 + 4 * tr;
                bu[nt] = *reinterpret_cast<const uint2*>(bp);
            }
#pragma unroll
            for (int mt = 0; mt < 4; mt++)
#pragma unroll
                for (int nt = 0; nt < 4; nt++)
                    mma_16816(acc[mt][nt],
                              au[mt][0].x, au[mt][1].x, au[mt][0].y, au[mt][1].y,
                              bu[nt].x, bu[nt].y);
        }
    }

#pragma unroll
    for (int mt = 0; mt < 4; mt++) {
        const int r1 = row0 + m0 + mt * 16 + tg;
        const int r2 = r1 + 8;
#pragma unroll
        for (int nt = 0; nt < 4; nt++) {
            const int cb = col0 + n0 + nt * 8 + 2 * tr;
            float2 bv = {0.f, 0.f};
            if (bias) bv = *reinterpret_cast<const float2*>(bias + cb);
            float2 o1, o2;
            o1.x = acc[mt][nt][0] + bv.x; o1.y = acc[mt][nt][1] + bv.y;
            o2.x = acc[mt][nt][2] + bv.x; o2.y = acc[mt][nt][3] + bv.y;
            *reinterpret_cast<float2*>(C + (size_t)r1 * DM + cb) = o1;
            *reinterpret_cast<float2*>(C + (size_t)r2 * DM + cb) = o2;
        }
    }
#undef PREFETCH
}

__global__ __launch_bounds__(256, 2)
void qkv_tc(const float* __restrict__ bq, const float* __restrict__ bk,
            const float* __restrict__ bv)
{
    const int z = blockIdx.z;
    const float* bias = (z == 0) ? bq : (z == 1) ? bk : bv;
    float* C          = (z == 0) ? g_q : (z == 1) ? g_k : g_v;
    gemm_body(g_xh, g_wh[z], bias, C, 0, DM / BKT);
}

// out projection split-K=2 (g_q/g_k are dead after attn_tc)
__global__ __launch_bounds__(256, 2)
void out_tc_split()
{
    const int z = blockIdx.z;
    float* C = (z == 0) ? g_q : g_k;
    gemm_body(g_ath, g_wh[3], nullptr, C, z * (DM / 2), DM / (2 * BKT));
}

__global__ __launch_bounds__(256)
void reduce_out(const float* __restrict__ bo, float* __restrict__ out)
{
    const int i = blockIdx.x * blockDim.x + threadIdx.x;      // float4 index
    const float4 a = reinterpret_cast<const float4*>(g_q)[i];
    const float4 b = reinterpret_cast<const float4*>(g_k)[i];
    const float4 bv = reinterpret_cast<const float4*>(bo)[i & (DM / 4 - 1)];
    float4 o;
    o.x = a.x + b.x + bv.x; o.y = a.y + b.y + bv.y;
    o.z = a.z + b.z + bv.z; o.w = a.w + b.w + bv.w;
    reinterpret_cast<float4*>(out)[i] = o;
}

// ---------------------------------------------------------------------------
// prep: z<4 -> W[K][N] f32 -> g_wh[z][N][K] fp16 (transpose + rne convert)
//       z==4 -> x f32 -> g_xh fp16
// ---------------------------------------------------------------------------
__global__ __launch_bounds__(256)
void prep(const float* __restrict__ x,
          const float* __restrict__ W0, const float* __restrict__ W1,
          const float* __restrict__ W2, const float* __restrict__ W3)
{
    const int z = blockIdx.z;
    if (z == 4) {
        const int linear = blockIdx.y * 64 + blockIdx.x;      // 0..4095 -> cover 1024x2048
        if (linear >= MROWS * DM / 1024) return;
        const int i0 = linear * 256 + threadIdx.x;            // float4 index
        float4 v = reinterpret_cast<const float4*>(x)[i0];
        __half2 h0 = __floats2half2_rn(v.x, v.y);
        __half2 h1 = __floats2half2_rn(v.z, v.w);
        uint2 o;
        o.x = *reinterpret_cast<uint32_t*>(&h0);
        o.y = *reinterpret_cast<uint32_t*>(&h1);
        reinterpret_cast<uint2*>(g_xh)[i0] = o;
        return;
    }
    __shared__ float tile[32][33];
    const float* W = (z == 0) ? W0 : (z == 1) ? W1 : (z == 2) ? W2 : W3;
    __half* T = g_wh[z];
    const int x0 = blockIdx.x * 32;     // N direction in W
    const int y0 = blockIdx.y * 32;     // K direction in W
    const int tx = threadIdx.x & 31;
    const int ty = threadIdx.x >> 5;    // 0..7
#pragma unroll
    for (int i = 0; i < 4; i++)
        tile[ty + i * 8][tx] = W[(size_t)(y0 + ty + i * 8) * DM + x0 + tx];
    __syncthreads();
#pragma unroll
    for (int i = 0; i < 4; i++)
        T[(size_t)(x0 + ty + i * 8) * DM + y0 + tx] = __float2half_rn(tile[tx][ty + i * 8]);
}

// ---------------------------------------------------------------------------
// Tensor-core attention (tf32). One CTA per (b,s) position m.
// Phase rotation cancels analytically: logits = (q.k)/sqrt(8); attn_i is
// discarded, so phase_shift never reaches the output.
// Output stored as fp16 (A operand of the out-projection).
// ---------------------------------------------------------------------------
__global__ __launch_bounds__(256)
void attn_tc()
{
    __shared__ float QT[8][264];   // [d][head]
    __shared__ float KT[8][264];
    __shared__ float VT[8][264];

    const int m    = blockIdx.x;
    const int t    = threadIdx.x;
    const int w    = t >> 5;
    const int lane = t & 31;
    const int tg   = lane >> 2;
    const int tr   = lane & 3;
    const int m0w  = w * 32;

    {
        const float4* q4 = reinterpret_cast<const float4*>(g_q + (size_t)m * DM) + 2 * t;
        const float4* k4 = reinterpret_cast<const float4*>(g_k + (size_t)m * DM) + 2 * t;
        const float4* v4 = reinterpret_cast<const float4*>(g_v + (size_t)m * DM) + 2 * t;
        float4 a0 = q4[0], a1 = q4[1];
        QT[0][t] = tf32r(a0.x); QT[1][t] = tf32r(a0.y);
        QT[2][t] = tf32r(a0.z); QT[3][t] = tf32r(a0.w);
        QT[4][t] = tf32r(a1.x); QT[5][t] = tf32r(a1.y);
        QT[6][t] = tf32r(a1.z); QT[7][t] = tf32r(a1.w);
        a0 = k4[0]; a1 = k4[1];
        KT[0][t] = tf32r(a0.x); KT[1][t] = tf32r(a0.y);
        KT[2][t] = tf32r(a0.z); KT[3][t] = tf32r(a0.w);
        KT[4][t] = tf32r(a1.x); KT[5][t] = tf32r(a1.y);
        KT[6][t] = tf32r(a1.z); KT[7][t] = tf32r(a1.w);
        a0 = v4[0]; a1 = v4[1];
        VT[0][t] = tf32r(a0.x); VT[1][t] = tf32r(a0.y);
        VT[2][t] = tf32r(a0.z); VT[3][t] = tf32r(a0.w);
        VT[4][t] = tf32r(a1.x); VT[5][t] = tf32r(a1.y);
        VT[6][t] = tf32r(a1.z); VT[7][t] = tf32r(a1.w);
    }
    __syncthreads();

    uint32_t aq0[4], aq1[4];
    aq0[0] = __float_as_uint(QT[tr    ][m0w + tg     ]);
    aq0[1] = __float_as_uint(QT[tr    ][m0w + tg +  8]);
    aq0[2] = __float_as_uint(QT[tr + 4][m0w + tg     ]);
    aq0[3] = __float_as_uint(QT[tr + 4][m0w + tg +  8]);
    aq1[0] = __float_as_uint(QT[tr    ][m0w + tg + 16]);
    aq1[1] = __float_as_uint(QT[tr    ][m0w + tg + 24]);
    aq1[2] = __float_as_uint(QT[tr + 4][m0w + tg + 16]);
    aq1[3] = __float_as_uint(QT[tr + 4][m0w + tg + 24]);

    float l[4] = {0.f, 0.f, 0.f, 0.f};
    float out0[4] = {0.f, 0.f, 0.f, 0.f};
    float out1[4] = {0.f, 0.f, 0.f, 0.f};

    for (int nt = 0; nt < 32; nt++) {
        const int g0 = nt * 8;
        uint32_t bs[2];
        bs[0] = __float_as_uint(KT[tr    ][g0 + tg]);
        bs[1] = __float_as_uint(KT[tr + 4][g0 + tg]);

        float c0[4] = {0.f, 0.f, 0.f, 0.f};
        float c1[4] = {0.f, 0.f, 0.f, 0.f};
        mma_1688(c0, aq0, bs);
        mma_1688(c1, aq1, bs);

        float p00 = fast_ex2(c0[0] * SCALE_LOG2E);
        float p01 = fast_ex2(c0[1] * SCALE_LOG2E);
        float p02 = fast_ex2(c0[2] * SCALE_LOG2E);
        float p03 = fast_ex2(c0[3] * SCALE_LOG2E);
        float p10 = fast_ex2(c1[0] * SCALE_LOG2E);
        float p11 = fast_ex2(c1[1] * SCALE_LOG2E);
        float p12 = fast_ex2(c1[2] * SCALE_LOG2E);
        float p13 = fast_ex2(c1[3] * SCALE_LOG2E);
        l[0] += p00 + p01;
        l[1] += p02 + p03;
        l[2] += p10 + p11;
        l[3] += p12 + p13;

        float2 vv = *reinterpret_cast<const float2*>(&VT[tg][g0 + 2 * tr]);
        uint32_t bv[2];
        bv[0] = __float_as_uint(vv.x);
        bv[1] = __float_as_uint(vv.y);

        uint32_t ap0[4], ap1[4];
        ap0[0] = tf32b(p00); ap0[1] = tf32b(p02); ap0[2] = tf32b(p01); ap0[3] = tf32b(p03);
        ap1[0] = tf32b(p10); ap1[1] = tf32b(p12); ap1[2] = tf32b(p11); ap1[3] = tf32b(p13);
        mma_1688(out0, ap0, bv);
        mma_1688(out1, ap1, bv);
    }

#pragma unroll
    for (int i = 0; i < 4; i++) {
        l[i] += __shfl_xor_sync(0xFFFFFFFFu, l[i], 1);
        l[i] += __shfl_xor_sync(0xFFFFFFFFu, l[i], 2);
    }
    const float i0 = 1.f / l[0], i1 = 1.f / l[1], i2 = 1.f / l[2], i3 = 1.f / l[3];

    // store fp16: row r, cols (2tr, 2tr+1) -> g_ath[m*2048 + r*8 + 2tr]
    __half* base = g_ath + (size_t)m * DM + 2 * tr;
    __half2 h;
    h = __floats2half2_rn(out0[0] * i0, out0[1] * i0);
    *reinterpret_cast<__half2*>(base + (m0w + tg     ) * HD) = h;
    h = __floats2half2_rn(out0[2] * i1, out0[3] * i1);
    *reinterpret_cast<__half2*>(base + (m0w + tg +  8) * HD) = h;
    h = __floats2half2_rn(out1[0] * i2, out1[1] * i2);
    *reinterpret_cast<__half2*>(base + (m0w + tg + 16) * HD) = h;
    h = __floats2half2_rn(out1[2] * i3, out1[3] * i3);
    *reinterpret_cast<__half2*>(base + (m0w + tg + 24) * HD) = h;
}

// ---------------------------------------------------------------------------
// Launch
// ---------------------------------------------------------------------------
extern "C" void kernel_launch(void* const* d_in, const int* in_sizes, int n_in,
                              void* d_out, int out_size)
{
    const float* x  = (const float*)d_in[0];
    // d_in[1] = phase_shift: cancels analytically, unused.
    const float* Wq = (const float*)d_in[2];
    const float* bq = (const float*)d_in[3];
    const float* Wk = (const float*)d_in[4];
    const float* bk = (const float*)d_in[5];
    const float* Wv = (const float*)d_in[6];
    const float* bv = (const float*)d_in[7];
    const float* Wo = (const float*)d_in[8];
    const float* bo = (const float*)d_in[9];
    float* out = (float*)d_out;

    cudaFuncSetAttribute(qkv_tc, cudaFuncAttributeMaxDynamicSharedMemorySize, SMEM_BYTES);
    cudaFuncSetAttribute(out_tc_split, cudaFuncAttributeMaxDynamicSharedMemorySize, SMEM_BYTES);

    prep<<<dim3(64, 64, 5), 256>>>(x, Wq, Wk, Wv, Wo);   // z<4: W transpose; z=4: x convert

    dim3 qkv_grid(DM / BNT, MROWS / BMT, 3);             // (16, 8, 3) = 384 CTAs
    qkv_tc<<<qkv_grid, 256, SMEM_BYTES>>>(bq, bk, bv);

    attn_tc<<<MROWS, 256>>>();

    dim3 out_grid(DM / BNT, MROWS / BMT, 2);             // (16, 8, 2) = 256 CTAs
    out_tc_split<<<out_grid, 256, SMEM_BYTES>>>();

    reduce_out<<<(MROWS * DM / 4) / 256, 256>>>(bo, out);
}